// round 1
// baseline (speedup 1.0000x reference)
#include <cuda_runtime.h>

// Problem constants (fixed by the reference).
#define BATCH 512
#define LSEQ  24576
#define LP    8192        // LSEQ / 3
#define HID   10

// Scratch for conv output (16 MB + pad for the prefetch overread).
__device__ float g_conv[(size_t)BATCH * LP + 4];

// ---------------------------------------------------------------------------
// Kernel 1: conv1d k=3 stride=3 + bias + relu.  Each thread produces 4 outputs
// from 3 float4 loads (12 contiguous inputs).
// ---------------------------------------------------------------------------
__global__ void conv_kernel(const float* __restrict__ x,
                            const float* __restrict__ cw,
                            const float* __restrict__ cb) {
    int idx = blockIdx.x * blockDim.x + threadIdx.x;   // 0 .. 512*2048-1
    int b = idx >> 11;          // 2048 quads per batch row
    int i = idx & 2047;
    if (b >= BATCH) return;

    const float4* xp = reinterpret_cast<const float4*>(x + (size_t)b * LSEQ + 12 * i);
    float4 a = xp[0];
    float4 m = xp[1];
    float4 c = xp[2];

    float w0 = cw[0], w1 = cw[1], w2 = cw[2], b0 = cb[0];

    float o0 = fmaf(a.x, w0, fmaf(a.y, w1, fmaf(a.z, w2, b0)));
    float o1 = fmaf(a.w, w0, fmaf(m.x, w1, fmaf(m.y, w2, b0)));
    float o2 = fmaf(m.z, w0, fmaf(m.w, w1, fmaf(c.x, w2, b0)));
    float o3 = fmaf(c.y, w0, fmaf(c.z, w1, fmaf(c.w, w2, b0)));

    float4 o;
    o.x = fmaxf(o0, 0.0f);
    o.y = fmaxf(o1, 0.0f);
    o.z = fmaxf(o2, 0.0f);
    o.w = fmaxf(o3, 0.0f);
    *reinterpret_cast<float4*>(g_conv + (size_t)b * LP + 4 * i) = o;
}

// ---------------------------------------------------------------------------
// Fast-but-accurate activations (EX2 + RCP approx, ~ulp-level error).
// ---------------------------------------------------------------------------
__device__ __forceinline__ float sigmoid_f(float x) {
    return __fdividef(1.0f, 1.0f + __expf(-x));
}
__device__ __forceinline__ float tanh_f(float x) {
    // tanh(x) = 1 - 2/(exp(2x)+1)
    return fmaf(-2.0f, __fdividef(1.0f, 1.0f + __expf(2.0f * x)), 1.0f);
}

// ---------------------------------------------------------------------------
// Kernel 2: LSTM scan + final MLP.
// One batch element per 16-lane warp segment; lane j<10 owns hidden unit j
// (gate rows i_j, f_j, g_j, o_j of w_hh live in its registers).
// Per step: 10x SHFL (h broadcast) + 40 FFMA + 4 sigmoid + 2 tanh.
// Conv values are streamed via float4 double-buffering (4-step prefetch).
// ---------------------------------------------------------------------------
__global__ void __launch_bounds__(128, 1)
lstm_kernel(const float* __restrict__ w_ih,
            const float* __restrict__ w_hh,
            const float* __restrict__ b_ih,
            const float* __restrict__ b_hh,
            const float* __restrict__ mlp_w,
            const float* __restrict__ mlp_b,
            float* __restrict__ out) {
    int tid = blockIdx.x * blockDim.x + threadIdx.x;
    int grp = tid >> 4;                 // batch element, 0..511
    int j   = tid & 15;                 // lane within segment
    int jc  = j < HID ? j : HID - 1;    // clamp idle lanes onto valid rows
    if (grp >= BATCH) return;

    // Recurrent weights for this hidden unit's 4 gates (torch order i,f,g,o).
    float wi[HID], wf[HID], wg[HID], wo[HID];
#pragma unroll
    for (int k = 0; k < HID; k++) {
        wi[k] = w_hh[(0 * HID + jc) * HID + k];
        wf[k] = w_hh[(1 * HID + jc) * HID + k];
        wg[k] = w_hh[(2 * HID + jc) * HID + k];
        wo[k] = w_hh[(3 * HID + jc) * HID + k];
    }
    float wxi = w_ih[0 * HID + jc];
    float wxf = w_ih[1 * HID + jc];
    float wxg = w_ih[2 * HID + jc];
    float wxo = w_ih[3 * HID + jc];
    float bbi = b_ih[0 * HID + jc] + b_hh[0 * HID + jc];
    float bbf = b_ih[1 * HID + jc] + b_hh[1 * HID + jc];
    float bbg = b_ih[2 * HID + jc] + b_hh[2 * HID + jc];
    float bbo = b_ih[3 * HID + jc] + b_hh[3 * HID + jc];

    float h = 0.0f, cst = 0.0f;

    const float* convp = g_conv + (size_t)grp * LP;
    float4 cur = *reinterpret_cast<const float4*>(convp);

    for (int t4 = 0; t4 < LP / 4; t4++) {
        // Prefetch next quad (padded overread on the last iteration).
        float4 nxt = *reinterpret_cast<const float4*>(convp + 4 * t4 + 4);

        float cts[4] = {cur.x, cur.y, cur.z, cur.w};
#pragma unroll
        for (int u = 0; u < 4; u++) {
            float ct = cts[u];
            float ai = fmaf(wxi, ct, bbi);
            float af = fmaf(wxf, ct, bbf);
            float ag = fmaf(wxg, ct, bbg);
            float ao = fmaf(wxo, ct, bbo);
#pragma unroll
            for (int k = 0; k < HID; k++) {
                float hk = __shfl_sync(0xffffffffu, h, k, 16);
                ai = fmaf(wi[k], hk, ai);
                af = fmaf(wf[k], hk, af);
                ag = fmaf(wg[k], hk, ag);
                ao = fmaf(wo[k], hk, ao);
            }
            float ig = sigmoid_f(ai);
            float fg = sigmoid_f(af);
            float gg = tanh_f(ag);
            float og = sigmoid_f(ao);
            cst = fmaf(fg, cst, ig * gg);
            h = og * tanh_f(cst);
        }
        cur = nxt;
    }

    // Final MLP: gather h_0..h_9, lanes 0..2 emit the 3 outputs.
    float hv[HID];
#pragma unroll
    for (int k = 0; k < HID; k++)
        hv[k] = __shfl_sync(0xffffffffu, h, k, 16);

    if (j < 3) {
        float acc = mlp_b[j];
#pragma unroll
        for (int k = 0; k < HID; k++)
            acc = fmaf(mlp_w[j * HID + k], hv[k], acc);
        out[grp * 3 + j] = acc;
    }
}

// ---------------------------------------------------------------------------
extern "C" void kernel_launch(void* const* d_in, const int* in_sizes, int n_in,
                              void* d_out, int out_size) {
    const float* x      = (const float*)d_in[0];
    const float* conv_w = (const float*)d_in[1];
    const float* conv_b = (const float*)d_in[2];
    const float* w_ih   = (const float*)d_in[3];
    const float* w_hh   = (const float*)d_in[4];
    const float* b_ih   = (const float*)d_in[5];
    const float* b_hh   = (const float*)d_in[6];
    const float* mlp_w  = (const float*)d_in[7];
    const float* mlp_b  = (const float*)d_in[8];
    float* out = (float*)d_out;

    // Conv: 512*2048 threads, 4 outputs each.
    {
        int total = BATCH * (LP / 4);
        int threads = 256;
        int blocks = (total + threads - 1) / threads;
        conv_kernel<<<blocks, threads>>>(x, conv_w, conv_b);
    }
    // LSTM: 512 groups * 16 lanes = 8192 threads.
    {
        int threads = 128;
        int blocks = (BATCH * 16) / threads;   // 64
        lstm_kernel<<<blocks, threads>>>(w_ih, w_hh, b_ih, b_hh, mlp_w, mlp_b, out);
    }
}